// round 15
// baseline (speedup 1.0000x reference)
#include <cuda_runtime.h>
#include <cuda_fp16.h>
#include <math.h>
#include <stdint.h>

#define Lc 6
#define Bc 32
#define Tc 256
#define SAc 512
#define STc 128
#define Dc 1024
#define Hc 16
#define HDc 64
#define DFFc 4096
#define OUTc 3
#define MTc (Bc*Tc)
#define MAc (Bc*SAc)
#define MSc (Bc*STc)
#define DDc (Dc*Dc)
#define WPLc (8*DDc + Dc*DFFc + DFFc*Dc)
#define QSz (Bc*Hc*Tc*HDc)
#define ASz (Bc*Hc*SAc*HDc)
#define TSz (Bc*Hc*STc*HDc)

__device__ float g_x[MTc*Dc];
__device__ float g_ada[Bc*6*Dc];
__device__ float g_sc[Bc*Dc];

__device__ __align__(256) __half g_h[MTc*Dc];
__device__ __align__(256) __half g_o[MTc*Dc];
__device__ __align__(256) __half g_ff[MTc*DFFc];
__device__ __align__(256) __half g_adp[MAc*Dc];
__device__ __align__(256) __half g_tsk[MSc*Dc];
__device__ __align__(256) __half g_w[Lc*WPLc];
__device__ __align__(256) __half g_qp[QSz], g_ksp[QSz];
__device__ __align__(256) __half g_kap[ASz], g_ktp[TSz];
__device__ __align__(256) __half g_qh[QSz], g_ksh[QSz], g_vsh[QSz];
__device__ __align__(256) __half g_kah[ASz], g_vah[ASz];
__device__ __align__(256) __half g_kth[TSz], g_vth[TSz];

__device__ __forceinline__ uint32_t smem_u32(const void* p) {
    uint32_t a;
    asm("{ .reg .u64 t; cvta.to.shared.u64 t, %1; cvt.u32.u64 %0, t; }" : "=r"(a) : "l"(p));
    return a;
}
#define MBAR_INIT(a, n) asm volatile("mbarrier.init.shared.b64 [%0], %1;" :: "r"(a), "r"(n) : "memory")
#define MBAR_EXPECT(a, tx) asm volatile("mbarrier.arrive.expect_tx.shared.b64 _, [%0], %1;" :: "r"(a), "r"(tx) : "memory")
#define MBAR_ARRIVE(a) asm volatile("mbarrier.arrive.shared.b64 _, [%0];" :: "r"(a) : "memory")
#define MBAR_WAIT(a, ph) do { \
    uint32_t _m = (a), _p = (ph), _d; \
    asm volatile("{ .reg .pred p; mbarrier.try_wait.parity.acquire.cta.shared::cta.b64 p, [%1], %2; selp.b32 %0,1,0,p; }" \
        : "=r"(_d) : "r"(_m), "r"(_p) : "memory"); \
    if (!_d) { \
        asm volatile("{ .reg .pred P1; WL_%=: mbarrier.try_wait.parity.acquire.cta.shared::cta.b64 P1, [%0], %1, 0x989680; @P1 bra.uni WD_%=; bra.uni WL_%=; WD_%=: }" \
            :: "r"(_m), "r"(_p) : "memory"); \
    } } while (0)
#define BULK8K(dst, src, bar) asm volatile( \
    "cp.async.bulk.shared::cluster.global.mbarrier::complete_tx::bytes [%0], [%1], 8192, [%2];" \
    :: "r"(dst), "l"(src), "r"(bar) : "memory")
#define FENCE_ASYNC() asm volatile("fence.proxy.async.shared::cta;" ::: "memory")
#define LDSM4(r, a) asm volatile( \
    "ldmatrix.sync.aligned.m8n8.x4.shared.b16 {%0,%1,%2,%3}, [%4];" \
    : "=r"((r)[0]), "=r"((r)[1]), "=r"((r)[2]), "=r"((r)[3]) : "r"(a))
#define LDSM4T(r, a) asm volatile( \
    "ldmatrix.sync.aligned.m8n8.x4.trans.shared.b16 {%0,%1,%2,%3}, [%4];" \
    : "=r"((r)[0]), "=r"((r)[1]), "=r"((r)[2]), "=r"((r)[3]) : "r"(a))

__device__ __forceinline__ void mma_f16(float* c, const uint32_t* a, const uint32_t* b) {
    asm volatile(
        "mma.sync.aligned.m16n8k16.row.col.f32.f16.f16.f32 "
        "{%0,%1,%2,%3}, {%4,%5,%6,%7}, {%8,%9}, {%0,%1,%2,%3};"
        : "+f"(c[0]), "+f"(c[1]), "+f"(c[2]), "+f"(c[3])
        : "r"(a[0]), "r"(a[1]), "r"(a[2]), "r"(a[3]), "r"(b[0]), "r"(b[1]));
}
__device__ __forceinline__ float gelu_t(float c) {
    float t = 0.7978845608028654f * (c + 0.044715f * c * c * c);
    return 0.5f * c * (1.f + tanhf(t));
}
// (row,col) of [M,Ncols] -> tile-major swizzled element offset (128x32 tiles, 8KB)
__device__ __forceinline__ size_t tile_off(int row, int col, int Ncols) {
    int r = row & 127;
    int cp = ((col >> 3) & 3) ^ ((r >> 1) & 3);
    return ((size_t)(row >> 7) * (Ncols >> 5) + (col >> 5)) * 4096 + r * 32 + cp * 8 + (col & 7);
}

// ---- fp16 single-pass MMA GEMM, 8-stage bulk ring ----
// EPI 0: C=acc+bias f32 | EPI 1: gelu->fp16 tile-major | EPI 2: X += gmod*(acc+bias)
// EPI 4: fused multi-output: seg0 -> plain fp16 o0 (+bias), seg1 -> plain o1 (or V if null),
//        seg2 -> swizzled per-(b,h) V. Plain layout: [(b*H+h)*S + s][64].
#define NST 8
#define STB 16384
#define GSMEM (NST*STB + 128)
template <int EPI>
__global__ __launch_bounds__(256) void mma_gemm(
    const __half* __restrict__ A, const __half* __restrict__ Bw,
    const float* __restrict__ bias, float* __restrict__ C, int M, int N, int K,
    const float* __restrict__ gmod, int gstride, float* __restrict__ X,
    __half* __restrict__ Cout, __half* __restrict__ Cout2, __half* __restrict__ CoutV,
    int sshift)
{
    extern __shared__ __align__(128) char smem[];
    const int tid = threadIdx.x;
    const uint32_t sb = smem_u32(smem);
    const uint32_t mbF = sb + NST * STB;
    const uint32_t mbE = mbF + 8 * NST;
    const int Kt = K >> 5;
    const size_t abase = (size_t)blockIdx.y * Kt * 4096;
    const size_t bbase = (size_t)blockIdx.x * Kt * 4096;

    if (tid == 0) {
        for (int s = 0; s < NST; s++) { MBAR_INIT(mbF + 8 * s, 1); MBAR_INIT(mbE + 8 * s, 256); }
        FENCE_ASYNC();
    }
    __syncthreads();

    auto issue = [&](int slot, int c) {
        uint32_t d = sb + slot * STB;
        uint32_t bar = mbF + 8 * slot;
        MBAR_EXPECT(bar, (uint32_t)STB);
        BULK8K(d,        A  + abase + (size_t)c * 4096, bar);
        BULK8K(d + 8192, Bw + bbase + (size_t)c * 4096, bar);
    };
    if (tid == 0)
        for (int s = 0; s < NST; s++) issue(s, s);

    const int w = tid >> 5, lane = tid & 31;
    const int wm = w >> 2, wn = w & 3;
    const int g = lane >> 2, t = lane & 3;

    const int ra  = (lane & 7) + ((lane >> 3) & 1) * 8;
    const int sa  = lane >> 4;
    const int s3a = (ra >> 1) & 3;
    const int rb  = (lane & 7) + (lane >> 4) * 8;
    const int sbk = (lane >> 3) & 1;
    const int s3b = (rb >> 1) & 3;

    uint32_t aoff[2][4], boff[2][2];
    #pragma unroll
    for (int ks = 0; ks < 2; ks++) {
        #pragma unroll
        for (int mt = 0; mt < 4; mt++)
            aoff[ks][mt] = (uint32_t)((wm * 64 + mt * 16 + ra) * 64 + (((ks * 2 + sa) ^ s3a) * 16));
        #pragma unroll
        for (int np = 0; np < 2; np++)
            boff[ks][np] = (uint32_t)((wn * 32 + np * 16 + rb) * 64 + (((ks * 2 + sbk) ^ s3b) * 16));
    }

    float acc[4][4][4];
    #pragma unroll
    for (int i = 0; i < 4; i++)
        #pragma unroll
        for (int j = 0; j < 4; j++)
            #pragma unroll
            for (int e = 0; e < 4; e++) acc[i][j][e] = 0.f;

    int slot = 0, rph = 0;
    for (int c = 0; c < Kt; c++) {
        MBAR_WAIT(mbF + 8 * slot, rph);
        const uint32_t base = sb + slot * STB;
        #pragma unroll
        for (int ks = 0; ks < 2; ks++) {
            uint32_t a4[4][4], b4[2][4];
            #pragma unroll
            for (int mt = 0; mt < 4; mt++) LDSM4(a4[mt], base + aoff[ks][mt]);
            #pragma unroll
            for (int np = 0; np < 2; np++) LDSM4(b4[np], base + 8192 + boff[ks][np]);
            #pragma unroll
            for (int mt = 0; mt < 4; mt++)
                #pragma unroll
                for (int nt = 0; nt < 4; nt++)
                    mma_f16(acc[mt][nt], a4[mt], &b4[nt >> 1][(nt & 1) * 2]);
        }
        MBAR_ARRIVE(mbE + 8 * slot);
        if (tid == 0 && c + NST < Kt) {
            MBAR_WAIT(mbE + 8 * slot, rph);
            FENCE_ASYNC();
            issue(slot, c + NST);
        }
        if (++slot == NST) { slot = 0; rph ^= 1; }
    }

    const int row0 = blockIdx.y * 128, col0 = blockIdx.x * 128;
    #pragma unroll
    for (int mt = 0; mt < 4; mt++) {
        const int row = row0 + wm * 64 + mt * 16 + g;
        #pragma unroll
        for (int nt = 0; nt < 4; nt++) {
            const int col = col0 + wn * 32 + nt * 8 + 2 * t;
            const float* a = acc[mt][nt];
            const bool useb = bias && (EPI != 4 || col < 1024);
            const float b0v = useb ? bias[col] : 0.f;
            const float b1v = useb ? bias[col + 1] : 0.f;
            const float v0 = a[0] + b0v, v1 = a[1] + b1v;
            const float v2 = a[2] + b0v, v3 = a[3] + b1v;
            if (EPI == 0) {
                *(float2*)(C + (size_t)row * N + col)       = make_float2(v0, v1);
                *(float2*)(C + (size_t)(row + 8) * N + col) = make_float2(v2, v3);
            } else if (EPI == 1) {
                size_t o0 = tile_off(row, col, N), o1 = tile_off(row + 8, col, N);
                *(__half2*)(Cout + o0) = __floats2half2_rn(gelu_t(v0), gelu_t(v1));
                *(__half2*)(Cout + o1) = __floats2half2_rn(gelu_t(v2), gelu_t(v3));
            } else if (EPI == 4) {
                const int nb = col >> 10;
                const int lc = col & 1023;
                const int hh = lc >> 6, d = lc & 63;
                const int Sm = (1 << sshift) - 1;
                __half2 p0 = __floats2half2_rn(v0, v1);
                __half2 p1 = __floats2half2_rn(v2, v3);
                const size_t hb = ((size_t)(row >> sshift) * Hc + hh) << sshift;
                if (nb == 0 || (nb == 1 && Cout2 != nullptr)) {
                    __half* dst = (nb == 0) ? Cout : Cout2;
                    size_t e0 = (hb + (row & Sm)) * 64 + d;
                    size_t e1 = (hb + ((row + 8) & Sm)) * 64 + d;
                    *(__half2*)(dst + e0) = p0;
                    *(__half2*)(dst + e1) = p1;
                } else {
                    size_t vb = hb * 64;
                    *(__half2*)(CoutV + vb + tile_off(row & Sm, d, 64))       = p0;
                    *(__half2*)(CoutV + vb + tile_off((row + 8) & Sm, d, 64)) = p1;
                }
            } else {
                const int bb = row >> 8;
                const float* gm = gmod + (size_t)bb * gstride;
                float2 x0 = *(float2*)(X + (size_t)row * N + col);
                float2 x1 = *(float2*)(X + (size_t)(row + 8) * N + col);
                x0.x += gm[col] * v0;  x0.y += gm[col + 1] * v1;
                x1.x += gm[col] * v2;  x1.y += gm[col + 1] * v3;
                *(float2*)(X + (size_t)row * N + col)       = x0;
                *(float2*)(X + (size_t)(row + 8) * N + col) = x1;
            }
        }
    }
}

// W[K,N] f32 -> tile-major swizzled fp16 of Wt[N,K]
__global__ __launch_bounds__(256) void wprep(const float* __restrict__ W,
    __half* __restrict__ Wh, int K, int N) {
    __shared__ float s[32 * 128];
    const int i = blockIdx.x, j = blockIdx.y;
    #pragma unroll
    for (int e = 0; e < 16; e++) {
        int idx = threadIdx.x + e * 256;
        int kk = idx >> 7, r = idx & 127;
        s[kk * 128 + r] = W[(size_t)(j * 32 + kk) * N + i * 128 + r];
    }
    __syncthreads();
    const size_t tbase = ((size_t)i * (K >> 5) + j) * 4096;
    #pragma unroll
    for (int e = 0; e < 2; e++) {
        int q = threadIdx.x * 2 + e;
        int r = q >> 2, cp = q & 3;
        int c = cp ^ ((r >> 1) & 3);
        uint32_t hw[4];
        #pragma unroll
        for (int u = 0; u < 4; u++) {
            __half2 hp = __floats2half2_rn(s[(c * 8 + 2 * u) * 128 + r],
                                           s[(c * 8 + 2 * u + 1) * 128 + r]);
            hw[u] = *(uint32_t*)&hp;
        }
        *(uint4*)(Wh + tbase + r * 32 + cp * 8) = make_uint4(hw[0], hw[1], hw[2], hw[3]);
    }
}

// fp32 [M,1024] row-major -> tile-major fp16
__global__ void split_tile(const float* __restrict__ s, __half* __restrict__ hi) {
    int idx = blockIdx.x * 256 + threadIdx.x;
    int row = idx >> 10, d = idx & 1023;
    hi[tile_off(row, d, Dc)] = __float2half(s[idx]);
}

__global__ void copy_kernel(const float* __restrict__ src, float* __restrict__ dst, int n) {
    int i = blockIdx.x * blockDim.x + threadIdx.x;
    if (i < n) dst[i] = src[i];
}
__global__ void silu_kernel(const float* __restrict__ c, float* __restrict__ out, int n) {
    int i = blockIdx.x * blockDim.x + threadIdx.x;
    if (i < n) { float x = c[i]; out[i] = x / (1.f + expf(-x)); }
}
__device__ __forceinline__ float block_reduce_sum(float v, float* red) {
    int tid = threadIdx.x;
    red[tid] = v;
    __syncthreads();
    #pragma unroll
    for (int s = 128; s > 0; s >>= 1) {
        if (tid < s) red[tid] += red[tid + s];
        __syncthreads();
    }
    float r = red[0];
    __syncthreads();
    return r;
}

__global__ void ln_mod(const float* __restrict__ x, const float* __restrict__ ada,
                       int off_shift, int off_scale, __half* __restrict__ hi) {
    __shared__ float red[256];
    int row = blockIdx.x, b = row / Tc, tid = threadIdx.x;
    const float* xr = x + (size_t)row * Dc;
    float v[4], s = 0.f;
    #pragma unroll
    for (int i = 0; i < 4; i++) { v[i] = xr[tid + i * 256]; s += v[i]; }
    float mean = block_reduce_sum(s, red) * (1.f / 1024.f);
    float sq = 0.f;
    #pragma unroll
    for (int i = 0; i < 4; i++) { float d = v[i] - mean; sq += d * d; }
    float rstd = rsqrtf(block_reduce_sum(sq, red) * (1.f / 1024.f) + 1e-5f);
    const float* ab = ada + (size_t)b * 6 * Dc;
    #pragma unroll
    for (int i = 0; i < 4; i++) {
        int d = tid + i * 256;
        float o = (v[i] - mean) * rstd * (1.f + ab[off_scale + d]) + ab[off_shift + d];
        hi[tile_off(row, d, Dc)] = __float2half(o);
    }
}

// RMSNorm + RoPE: read plain fp16 [(b*H+h)*S + s][64], write swizzled fp16 same indexing
__global__ void rmsrope_h2(const __half* __restrict__ in, const float* __restrict__ w,
                           int sLog, float cmul, const float* __restrict__ gate,
                           __half* __restrict__ outh) {
    int warp = (blockIdx.x * blockDim.x + threadIdx.x) >> 5;
    int lane = threadIdx.x & 31;
    int s = warp & ((1 << sLog) - 1);
    const __half* p = in + (size_t)warp * 64;
    float x0 = __half2float(p[lane]);
    float x1 = __half2float(p[lane + 32]);
    float ss = x0 * x0 + x1 * x1;
    #pragma unroll
    for (int o = 16; o; o >>= 1) ss += __shfl_xor_sync(0xffffffffu, ss, o);
    float inv = rsqrtf(ss * (1.f / 64.f) + 1e-6f);
    x0 = x0 * inv * w[lane];
    x1 = x1 * inv * w[lane + 32];
    float fr = (float)s * expf(-(float)lane * 0.28782313662425575f);
    float c = cosf(fr), sn = sinf(fr);
    float mult = cmul;
    if (gate) mult *= 1.f / (1.f + expf(-gate[0]));
    size_t base = ((size_t)warp - s) * 64;
    outh[base + tile_off(s, lane, 64)]      = __float2half((x0 * c - x1 * sn) * mult);
    outh[base + tile_off(s, lane + 32, 64)] = __float2half((x1 * c + x0 * sn) * mult);
}

__global__ void small_gemm_kernel(const float* __restrict__ A, const float* __restrict__ W,
                                  const float* __restrict__ bias, float* __restrict__ C,
                                  int Nn, int Kk) {
    int n = blockIdx.x * blockDim.x + threadIdx.x;
    int b = blockIdx.y;
    if (n >= Nn) return;
    const float* a = A + (size_t)b * Kk;
    float acc = 0.f;
    #pragma unroll 4
    for (int k = 0; k < Kk; k++) acc += a[k] * W[(size_t)k * Nn + n];
    C[(size_t)b * Nn + n] = acc + (bias ? bias[n] : 0.f);
}

// ---- fp16 tensor-core flash attention ----
#define FSMEM (16384 + 2*32768 + 64)
__global__ __launch_bounds__(256) void flash_mma(
    const __half* __restrict__ qh,
    const __half* __restrict__ ksh, const __half* __restrict__ vsh,
    const __half* __restrict__ kah, const __half* __restrict__ vah,
    const __half* __restrict__ kth, const __half* __restrict__ vth,
    __half* __restrict__ oh)
{
    extern __shared__ __align__(128) char smem[];
    const int tid = threadIdx.x, w = tid >> 5, lane = tid & 31;
    const int g = lane >> 2, t = lane & 3;
    const int bh = blockIdx.y, b = bh >> 4, h = bh & 15;
    const int qt = blockIdx.x;
    const uint32_t sb = smem_u32(smem);
    const uint32_t mbQ = sb + 81920, mbF = mbQ + 8;

    const __half* Ksrc[7];
    const __half* Vsrc[7];
    {
        const __half* kb = ksh + (size_t)bh * (Tc * 64);
        const __half* vb = vsh + (size_t)bh * (Tc * 64);
        Ksrc[0] = kb;         Vsrc[0] = vb;
        Ksrc[1] = kb + 8192;  Vsrc[1] = vb + 8192;
        const __half* ka = kah + (size_t)bh * (SAc * 64);
        const __half* va = vah + (size_t)bh * (SAc * 64);
        #pragma unroll
        for (int j = 0; j < 4; j++) { Ksrc[2 + j] = ka + j * 8192; Vsrc[2 + j] = va + j * 8192; }
        Ksrc[6] = kth + (size_t)bh * (STc * 64);
        Vsrc[6] = vth + (size_t)bh * (STc * 64);
    }

    auto issue = [&](int slot, int blk) {
        uint32_t kd = sb + 16384 + slot * 32768;
        uint32_t bar = mbF + 8 * slot;
        MBAR_EXPECT(bar, 32768u);
        BULK8K(kd,          Ksrc[blk],        bar);
        BULK8K(kd + 8192,   Ksrc[blk] + 4096, bar);
        BULK8K(kd + 16384,  Vsrc[blk],        bar);
        BULK8K(kd + 24576,  Vsrc[blk] + 4096, bar);
    };

    if (tid == 0) {
        MBAR_INIT(mbQ, 1);
        MBAR_INIT(mbF, 1);
        MBAR_INIT(mbF + 8, 1);
        FENCE_ASYNC();
        MBAR_EXPECT(mbQ, 16384u);
        const __half* qsrc = qh + (size_t)bh * (Tc * 64) + qt * 8192;
        BULK8K(sb,        qsrc,        mbQ);
        BULK8K(sb + 8192, qsrc + 4096, mbQ);
        issue(0, 0);
        issue(1, 1);
    }
    __syncthreads();

    const int ra  = (lane & 7) + ((lane >> 3) & 1) * 8;
    const int sa  = lane >> 4;
    const int rbn = (lane & 7) + (lane >> 4) * 8;
    const int sbk = (lane >> 3) & 1;
    const int rvk = (lane & 7) + ((lane >> 3) & 1) * 8;
    const int svd = (lane >> 4) & 1;

    MBAR_WAIT(mbQ, 0);
    uint32_t qa[4][4];
    #pragma unroll
    for (int ks = 0; ks < 4; ks++)
        LDSM4(qa[ks], sb + 2 * (uint32_t)tile_off(16 * w + ra, ks * 16 + sa * 8, 64));

    float sO[8][4];
    #pragma unroll
    for (int i = 0; i < 8; i++)
        #pragma unroll
        for (int e = 0; e < 4; e++) sO[i][e] = 0.f;
    float m0 = -1e30f, m1 = -1e30f, l0 = 0.f, l1 = 0.f;

    for (int blk = 0; blk < 7; blk++) {
        const int slot = blk & 1;
        MBAR_WAIT(mbF + 8 * slot, (blk >> 1) & 1);
        const uint32_t kbase = sb + 16384 + slot * 32768;
        const uint32_t vbase = kbase + 16384;

        float sc[16][4];
        #pragma unroll
        for (int i = 0; i < 16; i++)
            #pragma unroll
            for (int e = 0; e < 4; e++) sc[i][e] = 0.f;

        #pragma unroll
        for (int ks = 0; ks < 4; ks++) {
            #pragma unroll
            for (int np = 0; np < 8; np++) {
                uint32_t b4[4];
                LDSM4(b4, kbase + 2 * (uint32_t)tile_off(16 * np + rbn, ks * 16 + sbk * 8, 64));
                mma_f16(sc[2 * np],     qa[ks], &b4[0]);
                mma_f16(sc[2 * np + 1], qa[ks], &b4[2]);
            }
        }

        float tm0 = -1e30f, tm1 = -1e30f;
        #pragma unroll
        for (int i = 0; i < 16; i++) {
            tm0 = fmaxf(tm0, fmaxf(sc[i][0], sc[i][1]));
            tm1 = fmaxf(tm1, fmaxf(sc[i][2], sc[i][3]));
        }
        tm0 = fmaxf(tm0, __shfl_xor_sync(0xffffffffu, tm0, 1));
        tm0 = fmaxf(tm0, __shfl_xor_sync(0xffffffffu, tm0, 2));
        tm1 = fmaxf(tm1, __shfl_xor_sync(0xffffffffu, tm1, 1));
        tm1 = fmaxf(tm1, __shfl_xor_sync(0xffffffffu, tm1, 2));
        float nm0 = fmaxf(m0, tm0), nm1 = fmaxf(m1, tm1);
        float cr0 = __expf(m0 - nm0), cr1 = __expf(m1 - nm1);
        l0 *= cr0; l1 *= cr1;
        #pragma unroll
        for (int i = 0; i < 8; i++) {
            sO[i][0] *= cr0; sO[i][1] *= cr0;
            sO[i][2] *= cr1; sO[i][3] *= cr1;
        }
        m0 = nm0; m1 = nm1;

        uint32_t pf[16][2];
        #pragma unroll
        for (int i = 0; i < 16; i++) {
            float p0 = __expf(sc[i][0] - nm0), p1 = __expf(sc[i][1] - nm0);
            float p2 = __expf(sc[i][2] - nm1), p3 = __expf(sc[i][3] - nm1);
            l0 += p0 + p1;
            l1 += p2 + p3;
            __half2 h0 = __floats2half2_rn(p0, p1), h1 = __floats2half2_rn(p2, p3);
            pf[i][0] = *(uint32_t*)&h0;
            pf[i][1] = *(uint32_t*)&h1;
        }

        #pragma unroll
        for (int u = 0; u < 8; u++) {
            uint32_t pa[4] = {pf[2*u][0], pf[2*u][1], pf[2*u+1][0], pf[2*u+1][1]};
            #pragma unroll
            for (int nd = 0; nd < 4; nd++) {
                uint32_t vb4[4];
                LDSM4T(vb4, vbase + 2 * (uint32_t)tile_off(16 * u + rvk, 16 * nd + svd * 8, 64));
                mma_f16(sO[2 * nd],     pa, &vb4[0]);
                mma_f16(sO[2 * nd + 1], pa, &vb4[2]);
            }
        }
        __syncthreads();
        if (tid == 0 && blk + 2 < 7) { FENCE_ASYNC(); issue(slot, blk + 2); }
    }

    l0 += __shfl_xor_sync(0xffffffffu, l0, 1);
    l0 += __shfl_xor_sync(0xffffffffu, l0, 2);
    l1 += __shfl_xor_sync(0xffffffffu, l1, 1);
    l1 += __shfl_xor_sync(0xffffffffu, l1, 2);
    float i0 = 1.f / l0, i1 = 1.f / l1;

    int orow = b * Tc + qt * 128 + 16 * w + g;
    #pragma unroll
    for (int nt = 0; nt < 8; nt++) {
        int col = h * 64 + nt * 8 + 2 * t;
        __half2 v0 = __floats2half2_rn(sO[nt][0] * i0, sO[nt][1] * i0);
        __half2 v1 = __floats2half2_rn(sO[nt][2] * i1, sO[nt][3] * i1);
        *(__half2*)(oh + tile_off(orow, col, Dc))     = v0;
        *(__half2*)(oh + tile_off(orow + 8, col, Dc)) = v1;
    }
}

__global__ void final_kernel(const float* __restrict__ x, const float* __restrict__ lw,
                             const float* __restrict__ lb, const float* __restrict__ Wout,
                             const float* __restrict__ bout, float* __restrict__ out) {
    __shared__ float red[256];
    int row = blockIdx.x, tid = threadIdx.x;
    const float* xr = x + (size_t)row * Dc;
    float v[4], s = 0.f;
    #pragma unroll
    for (int i = 0; i < 4; i++) { v[i] = xr[tid + i * 256]; s += v[i]; }
    float mean = block_reduce_sum(s, red) * (1.f / 1024.f);
    float sq = 0.f;
    #pragma unroll
    for (int i = 0; i < 4; i++) { float d = v[i] - mean; sq += d * d; }
    float rstd = rsqrtf(block_reduce_sum(sq, red) * (1.f / 1024.f) + 1e-5f);
    float p0 = 0.f, p1 = 0.f, p2 = 0.f;
    #pragma unroll
    for (int i = 0; i < 4; i++) {
        int d = tid + i * 256;
        float y = (v[i] - mean) * rstd * lw[d] + lb[d];
        p0 = fmaf(y, Wout[d * OUTc + 0], p0);
        p1 = fmaf(y, Wout[d * OUTc + 1], p1);
        p2 = fmaf(y, Wout[d * OUTc + 2], p2);
    }
    p0 = block_reduce_sum(p0, red);
    p1 = block_reduce_sum(p1, red);
    p2 = block_reduce_sum(p2, red);
    if (tid == 0) {
        out[row * OUTc + 0] = p0 + bout[0];
        out[row * OUTc + 1] = p1 + bout[1];
        out[row * OUTc + 2] = p2 + bout[2];
    }
}

extern "C" void kernel_launch(void* const* d_in, const int* in_sizes, int n_in,
                              void* d_out, int out_size)
{
    (void)in_sizes; (void)n_in; (void)out_size;
    const float* x    = (const float*)d_in[0];
    const float* cond = (const float*)d_in[1];
    const float* adp  = (const float*)d_in[2];
    const float* task = (const float*)d_in[3];
    const float* Wq   = (const float*)d_in[4];
    const float* bq   = (const float*)d_in[5];
    const float* Wks  = (const float*)d_in[6];
    const float* Wvs  = (const float*)d_in[7];
    const float* Wka  = (const float*)d_in[8];
    const float* Wva  = (const float*)d_in[9];
    const float* Wkt  = (const float*)d_in[10];
    const float* Wvt  = (const float*)d_in[11];
    const float* Wo   = (const float*)d_in[12];
    const float* bo   = (const float*)d_in[13];
    const float* qnw  = (const float*)d_in[14];
    const float* knw  = (const float*)d_in[15];
    const float* gate = (const float*)d_in[16];
    const float* Wada = (const float*)d_in[17];
    const float* bada = (const float*)d_in[18];
    const float* W1   = (const float*)d_in[19];
    const float* b1   = (const float*)d_in[20];
    const float* W2   = (const float*)d_in[21];
    const float* b2   = (const float*)d_in[22];
    const float* lnfw = (const float*)d_in[23];
    const float* lnfb = (const float*)d_in[24];
    const float* Wout = (const float*)d_in[25];
    const float* bout = (const float*)d_in[26];
    float* out = (float*)d_out;

    cudaFuncSetAttribute(mma_gemm<0>, cudaFuncAttributeMaxDynamicSharedMemorySize, GSMEM);
    cudaFuncSetAttribute(mma_gemm<1>, cudaFuncAttributeMaxDynamicSharedMemorySize, GSMEM);
    cudaFuncSetAttribute(mma_gemm<2>, cudaFuncAttributeMaxDynamicSharedMemorySize, GSMEM);
    cudaFuncSetAttribute(mma_gemm<4>, cudaFuncAttributeMaxDynamicSharedMemorySize, GSMEM);
    cudaFuncSetAttribute(flash_mma,   cudaFuncAttributeMaxDynamicSharedMemorySize, FSMEM);

    float *px, *pada, *psc;
    __half *ph, *po, *pf, *pa, *pt, *pw;
    __half *pqp, *pksp, *pkap, *pktp;
    __half *pqh, *pksh, *pvsh, *pkah, *pvah, *pkth, *pvth;
    cudaGetSymbolAddress((void**)&px,  g_x);
    cudaGetSymbolAddress((void**)&pada, g_ada);
    cudaGetSymbolAddress((void**)&psc,  g_sc);
    cudaGetSymbolAddress((void**)&ph, g_h);
    cudaGetSymbolAddress((void**)&po, g_o);
    cudaGetSymbolAddress((void**)&pf, g_ff);
    cudaGetSymbolAddress((void**)&pa, g_adp);
    cudaGetSymbolAddress((void**)&pt, g_tsk);
    cudaGetSymbolAddress((void**)&pw, g_w);
    cudaGetSymbolAddress((void**)&pqp,  g_qp);
    cudaGetSymbolAddress((void**)&pksp, g_ksp);
    cudaGetSymbolAddress((void**)&pkap, g_kap);
    cudaGetSymbolAddress((void**)&pktp, g_ktp);
    cudaGetSymbolAddress((void**)&pqh,  g_qh);
    cudaGetSymbolAddress((void**)&pksh, g_ksh);
    cudaGetSymbolAddress((void**)&pvsh, g_vsh);
    cudaGetSymbolAddress((void**)&pkah, g_kah);
    cudaGetSymbolAddress((void**)&pvah, g_vah);
    cudaGetSymbolAddress((void**)&pkth, g_kth);
    cudaGetSymbolAddress((void**)&pvth, g_vth);

    copy_kernel<<<(MTc*Dc)/256, 256>>>(x, px, MTc*Dc);
    silu_kernel<<<(Bc*Dc)/256, 256>>>(cond, psc, Bc*Dc);
    split_tile<<<(MAc*Dc)/256, 256>>>(adp,  pa);
    split_tile<<<(MSc*Dc)/256, 256>>>(task, pt);

    const float* wsrc[8] = {Wq, Wks, Wvs, Wka, Wva, Wkt, Wvt, Wo};
    for (int i = 0; i < Lc; i++) {
        size_t base = (size_t)i * WPLc;
        for (int mtx = 0; mtx < 8; mtx++)
            wprep<<<dim3(Dc/128, Dc/32), 256>>>(
                wsrc[mtx] + (size_t)i * DDc, pw + base + (size_t)mtx * DDc, Dc, Dc);
        wprep<<<dim3(DFFc/128, Dc/32), 256>>>(
            W1 + (size_t)i * Dc * DFFc, pw + base + 8*DDc, Dc, DFFc);
        wprep<<<dim3(Dc/128, DFFc/32), 256>>>(
            W2 + (size_t)i * DFFc * Dc, pw + base + 8*DDc + (size_t)Dc*DFFc, DFFc, Dc);
    }

    for (int i = 0; i < Lc; i++) {
        size_t wb = (size_t)i * WPLc;
        __half* wqkv = pw + wb;                       // q,k,v weights contiguous
        __half* wka2 = pw + wb + 3*(size_t)DDc;       // ka,va contiguous
        __half* wkt2 = pw + wb + 5*(size_t)DDc;       // kt,vt contiguous
        __half* wo2  = pw + wb + 7*(size_t)DDc;
        __half* w1   = pw + wb + 8*(size_t)DDc;
        __half* w2   = pw + wb + 8*(size_t)DDc + (size_t)Dc*DFFc;

        small_gemm_kernel<<<dim3((6*Dc)/256, Bc), 256>>>(
            psc, Wada + (size_t)i*Dc*6*Dc, bada + (size_t)i*6*Dc, pada, 6*Dc, Dc);

        ln_mod<<<MTc, 256>>>(px, pada, 0, Dc, ph);

        // fused Q|K|V (bias on Q only), fused adp K|V, fused task K|V
        mma_gemm<4><<<dim3(3*Dc/128, MTc/128), 256, GSMEM>>>(ph, wqkv, bq + (size_t)i*Dc, nullptr,
            MTc, 3*Dc, Dc, nullptr, 0, nullptr, pqp, pksp, pvsh, 8);
        mma_gemm<4><<<dim3(2*Dc/128, MAc/128), 256, GSMEM>>>(pa, wka2, nullptr, nullptr,
            MAc, 2*Dc, Dc, nullptr, 0, nullptr, pkap, nullptr, pvah, 9);
        mma_gemm<4><<<dim3(2*Dc/128, MSc/128), 256, GSMEM>>>(pt, wkt2, nullptr, nullptr,
            MSc, 2*Dc, Dc, nullptr, 0, nullptr, pktp, nullptr, pvth, 7);

        rmsrope_h2<<<(MTc*Hc*32)/256, 256>>>(pqp,  qnw + (size_t)i*HDc, 8, 0.125f, nullptr, pqh);
        rmsrope_h2<<<(MTc*Hc*32)/256, 256>>>(pksp, knw + (size_t)i*HDc, 8, 1.f,    nullptr, pksh);
        rmsrope_h2<<<(MAc*Hc*32)/256, 256>>>(pkap, knw + (size_t)i*HDc, 9, 1.f,    nullptr, pkah);
        rmsrope_h2<<<(MSc*Hc*32)/256, 256>>>(pktp, knw + (size_t)i*HDc, 7, 1.f,    gate + i, pkth);

        flash_mma<<<dim3(Tc/128, Bc*Hc), 256, FSMEM>>>(pqh, pksh, pvsh, pkah, pvah, pkth, pvth, po);

        mma_gemm<2><<<dim3(Dc/128, MTc/128), 256, GSMEM>>>(po, wo2, bo + (size_t)i*Dc, nullptr,
            MTc, Dc, Dc, pada + 2*Dc, 6*Dc, px, nullptr, nullptr, nullptr, 0);

        ln_mod<<<MTc, 256>>>(px, pada, 3*Dc, 4*Dc, ph);

        mma_gemm<1><<<dim3(DFFc/128, MTc/128), 256, GSMEM>>>(ph, w1, b1 + (size_t)i*DFFc, nullptr,
            MTc, DFFc, Dc, nullptr, 0, nullptr, pf, nullptr, nullptr, 0);

        mma_gemm<2><<<dim3(Dc/128, MTc/128), 256, GSMEM>>>(pf, w2, b2 + (size_t)i*Dc, nullptr,
            MTc, Dc, DFFc, pada + 5*Dc, 6*Dc, px, nullptr, nullptr, nullptr, 0);
    }

    final_kernel<<<MTc, 256>>>(px, lnfw, lnfb, Wout, bout, out);
}

// round 17
// speedup vs baseline: 1.0583x; 1.0583x over previous
#include <cuda_runtime.h>
#include <cuda_fp16.h>
#include <math.h>
#include <stdint.h>

#define Lc 6
#define Bc 32
#define Tc 256
#define SAc 512
#define STc 128
#define Dc 1024
#define Hc 16
#define HDc 64
#define DFFc 4096
#define OUTc 3
#define MTc (Bc*Tc)
#define MAc (Bc*SAc)
#define MSc (Bc*STc)
#define DDc (Dc*Dc)
#define WPLc (8*DDc + Dc*DFFc + DFFc*Dc)
#define QSz (Bc*Hc*Tc*HDc)
#define ASz (Bc*Hc*SAc*HDc)
#define TSz (Bc*Hc*STc*HDc)
#define ADAL (Bc*6*Dc)

__device__ float g_x[MTc*Dc];
__device__ float g_ada[Lc*ADAL];
__device__ float g_sc[Bc*Dc];

__device__ __align__(256) __half g_h[MTc*Dc];
__device__ __align__(256) __half g_o[MTc*Dc];
__device__ __align__(256) __half g_ff[MTc*DFFc];
__device__ __align__(256) __half g_adp[MAc*Dc];
__device__ __align__(256) __half g_tsk[MSc*Dc];
__device__ __align__(256) __half g_w[Lc*WPLc];
__device__ __align__(256) __half g_qp[QSz], g_ksp[QSz];
__device__ __align__(256) __half g_kap[ASz], g_ktp[TSz];
__device__ __align__(256) __half g_qh[QSz], g_ksh[QSz], g_vsh[QSz];
__device__ __align__(256) __half g_kah[ASz], g_vah[ASz];
__device__ __align__(256) __half g_kth[TSz], g_vth[TSz];

__device__ __forceinline__ uint32_t smem_u32(const void* p) {
    uint32_t a;
    asm("{ .reg .u64 t; cvta.to.shared.u64 t, %1; cvt.u32.u64 %0, t; }" : "=r"(a) : "l"(p));
    return a;
}
#define MBAR_INIT(a, n) asm volatile("mbarrier.init.shared.b64 [%0], %1;" :: "r"(a), "r"(n) : "memory")
#define MBAR_EXPECT(a, tx) asm volatile("mbarrier.arrive.expect_tx.shared.b64 _, [%0], %1;" :: "r"(a), "r"(tx) : "memory")
#define MBAR_ARRIVE(a) asm volatile("mbarrier.arrive.shared.b64 _, [%0];" :: "r"(a) : "memory")
#define MBAR_WAIT(a, ph) do { \
    uint32_t _m = (a), _p = (ph), _d; \
    asm volatile("{ .reg .pred p; mbarrier.try_wait.parity.acquire.cta.shared::cta.b64 p, [%1], %2; selp.b32 %0,1,0,p; }" \
        : "=r"(_d) : "r"(_m), "r"(_p) : "memory"); \
    if (!_d) { \
        asm volatile("{ .reg .pred P1; WL_%=: mbarrier.try_wait.parity.acquire.cta.shared::cta.b64 P1, [%0], %1, 0x989680; @P1 bra.uni WD_%=; bra.uni WL_%=; WD_%=: }" \
            :: "r"(_m), "r"(_p) : "memory"); \
    } } while (0)
#define BULK8K(dst, src, bar) asm volatile( \
    "cp.async.bulk.shared::cluster.global.mbarrier::complete_tx::bytes [%0], [%1], 8192, [%2];" \
    :: "r"(dst), "l"(src), "r"(bar) : "memory")
#define FENCE_ASYNC() asm volatile("fence.proxy.async.shared::cta;" ::: "memory")
#define LDSM4(r, a) asm volatile( \
    "ldmatrix.sync.aligned.m8n8.x4.shared.b16 {%0,%1,%2,%3}, [%4];" \
    : "=r"((r)[0]), "=r"((r)[1]), "=r"((r)[2]), "=r"((r)[3]) : "r"(a))
#define LDSM4T(r, a) asm volatile( \
    "ldmatrix.sync.aligned.m8n8.x4.trans.shared.b16 {%0,%1,%2,%3}, [%4];" \
    : "=r"((r)[0]), "=r"((r)[1]), "=r"((r)[2]), "=r"((r)[3]) : "r"(a))

__device__ __forceinline__ void mma_f16(float* c, const uint32_t* a, const uint32_t* b) {
    asm volatile(
        "mma.sync.aligned.m16n8k16.row.col.f32.f16.f16.f32 "
        "{%0,%1,%2,%3}, {%4,%5,%6,%7}, {%8,%9}, {%0,%1,%2,%3};"
        : "+f"(c[0]), "+f"(c[1]), "+f"(c[2]), "+f"(c[3])
        : "r"(a[0]), "r"(a[1]), "r"(a[2]), "r"(a[3]), "r"(b[0]), "r"(b[1]));
}
__device__ __forceinline__ float gelu_t(float c) {
    float t = 0.7978845608028654f * (c + 0.044715f * c * c * c);
    return 0.5f * c * (1.f + tanhf(t));
}
// (row,col) of [M,Ncols] -> tile-major swizzled element offset (128x32 tiles, 8KB)
__device__ __forceinline__ size_t tile_off(int row, int col, int Ncols) {
    int r = row & 127;
    int cp = ((col >> 3) & 3) ^ ((r >> 1) & 3);
    return ((size_t)(row >> 7) * (Ncols >> 5) + (col >> 5)) * 4096 + r * 32 + cp * 8 + (col & 7);
}

// ---- fp16 single-pass MMA GEMM, 8-stage bulk ring ----
// EPI 0: C=acc+bias f32 | EPI 1: gelu->fp16 tile-major | EPI 2: X += gmod*(acc+bias)
// EPI 4: fused multi-output: seg0 -> plain fp16 o0 (+bias), seg1 -> plain o1 (or V if null),
//        seg2 -> swizzled per-(b,h) V. Plain layout: [(b*H+h)*S + s][64].
#define NST 8
#define STB 16384
#define GSMEM (NST*STB + 128)
template <int EPI>
__global__ __launch_bounds__(256) void mma_gemm(
    const __half* __restrict__ A, const __half* __restrict__ Bw,
    const float* __restrict__ bias, float* __restrict__ C, int M, int N, int K,
    const float* __restrict__ gmod, int gstride, float* __restrict__ X,
    __half* __restrict__ Cout, __half* __restrict__ Cout2, __half* __restrict__ CoutV,
    int sshift)
{
    extern __shared__ __align__(128) char smem[];
    const int tid = threadIdx.x;
    const uint32_t sb = smem_u32(smem);
    const uint32_t mbF = sb + NST * STB;
    const uint32_t mbE = mbF + 8 * NST;
    const int Kt = K >> 5;
    const size_t abase = (size_t)blockIdx.y * Kt * 4096;
    const size_t bbase = (size_t)blockIdx.x * Kt * 4096;

    if (tid == 0) {
        for (int s = 0; s < NST; s++) { MBAR_INIT(mbF + 8 * s, 1); MBAR_INIT(mbE + 8 * s, 8); }
        FENCE_ASYNC();
    }
    __syncthreads();

    auto issue = [&](int slot, int c) {
        uint32_t d = sb + slot * STB;
        uint32_t bar = mbF + 8 * slot;
        MBAR_EXPECT(bar, (uint32_t)STB);
        BULK8K(d,        A  + abase + (size_t)c * 4096, bar);
        BULK8K(d + 8192, Bw + bbase + (size_t)c * 4096, bar);
    };
    if (tid == 0)
        for (int s = 0; s < NST; s++) issue(s, s);

    const int w = tid >> 5, lane = tid & 31;
    const int wm = w >> 2, wn = w & 3;
    const int g = lane >> 2, t = lane & 3;

    const int ra  = (lane & 7) + ((lane >> 3) & 1) * 8;
    const int sa  = lane >> 4;
    const int s3a = (ra >> 1) & 3;
    const int rb  = (lane & 7) + (lane >> 4) * 8;
    const int sbk = (lane >> 3) & 1;
    const int s3b = (rb >> 1) & 3;

    uint32_t aoff[2][4], boff[2][2];
    #pragma unroll
    for (int ks = 0; ks < 2; ks++) {
        #pragma unroll
        for (int mt = 0; mt < 4; mt++)
            aoff[ks][mt] = (uint32_t)((wm * 64 + mt * 16 + ra) * 64 + (((ks * 2 + sa) ^ s3a) * 16));
        #pragma unroll
        for (int np = 0; np < 2; np++)
            boff[ks][np] = (uint32_t)((wn * 32 + np * 16 + rb) * 64 + (((ks * 2 + sbk) ^ s3b) * 16));
    }

    float acc[4][4][4];
    #pragma unroll
    for (int i = 0; i < 4; i++)
        #pragma unroll
        for (int j = 0; j < 4; j++)
            #pragma unroll
            for (int e = 0; e < 4; e++) acc[i][j][e] = 0.f;

    int slot = 0, rph = 0;
    for (int c = 0; c < Kt; c++) {
        MBAR_WAIT(mbF + 8 * slot, rph);
        const uint32_t base = sb + slot * STB;
        #pragma unroll
        for (int ks = 0; ks < 2; ks++) {
            uint32_t a4[4][4], b4[2][4];
            #pragma unroll
            for (int mt = 0; mt < 4; mt++) LDSM4(a4[mt], base + aoff[ks][mt]);
            #pragma unroll
            for (int np = 0; np < 2; np++) LDSM4(b4[np], base + 8192 + boff[ks][np]);
            #pragma unroll
            for (int mt = 0; mt < 4; mt++)
                #pragma unroll
                for (int nt = 0; nt < 4; nt++)
                    mma_f16(acc[mt][nt], a4[mt], &b4[nt >> 1][(nt & 1) * 2]);
        }
        if (lane == 0) MBAR_ARRIVE(mbE + 8 * slot);
        if (tid == 0 && c + NST < Kt) {
            MBAR_WAIT(mbE + 8 * slot, rph);
            FENCE_ASYNC();
            issue(slot, c + NST);
        }
        if (++slot == NST) { slot = 0; rph ^= 1; }
    }

    const int row0 = blockIdx.y * 128, col0 = blockIdx.x * 128;
    #pragma unroll
    for (int mt = 0; mt < 4; mt++) {
        const int row = row0 + wm * 64 + mt * 16 + g;
        #pragma unroll
        for (int nt = 0; nt < 4; nt++) {
            const int col = col0 + wn * 32 + nt * 8 + 2 * t;
            const float* a = acc[mt][nt];
            const bool useb = bias && (EPI != 4 || col < 1024);
            const float b0v = useb ? bias[col] : 0.f;
            const float b1v = useb ? bias[col + 1] : 0.f;
            const float v0 = a[0] + b0v, v1 = a[1] + b1v;
            const float v2 = a[2] + b0v, v3 = a[3] + b1v;
            if (EPI == 0) {
                *(float2*)(C + (size_t)row * N + col)       = make_float2(v0, v1);
                *(float2*)(C + (size_t)(row + 8) * N + col) = make_float2(v2, v3);
            } else if (EPI == 1) {
                size_t o0 = tile_off(row, col, N), o1 = tile_off(row + 8, col, N);
                *(__half2*)(Cout + o0) = __floats2half2_rn(gelu_t(v0), gelu_t(v1));
                *(__half2*)(Cout + o1) = __floats2half2_rn(gelu_t(v2), gelu_t(v3));
            } else if (EPI == 4) {
                const int nb = col >> 10;
                const int lc = col & 1023;
                const int hh = lc >> 6, d = lc & 63;
                const int Sm = (1 << sshift) - 1;
                __half2 p0 = __floats2half2_rn(v0, v1);
                __half2 p1 = __floats2half2_rn(v2, v3);
                const size_t hb = ((size_t)(row >> sshift) * Hc + hh) << sshift;
                if (nb == 0 || (nb == 1 && Cout2 != nullptr)) {
                    __half* dst = (nb == 0) ? Cout : Cout2;
                    size_t e0 = (hb + (row & Sm)) * 64 + d;
                    size_t e1 = (hb + ((row + 8) & Sm)) * 64 + d;
                    *(__half2*)(dst + e0) = p0;
                    *(__half2*)(dst + e1) = p1;
                } else {
                    size_t vb = hb * 64;
                    *(__half2*)(CoutV + vb + tile_off(row & Sm, d, 64))       = p0;
                    *(__half2*)(CoutV + vb + tile_off((row + 8) & Sm, d, 64)) = p1;
                }
            } else {
                const int bb = row >> 8;
                const float* gm = gmod + (size_t)bb * gstride;
                float2 x0 = *(float2*)(X + (size_t)row * N + col);
                float2 x1 = *(float2*)(X + (size_t)(row + 8) * N + col);
                x0.x += gm[col] * v0;  x0.y += gm[col + 1] * v1;
                x1.x += gm[col] * v2;  x1.y += gm[col + 1] * v3;
                *(float2*)(X + (size_t)row * N + col)       = x0;
                *(float2*)(X + (size_t)(row + 8) * N + col) = x1;
            }
        }
    }
}

// W[K,N] f32 -> tile-major swizzled fp16 of Wt[N,K]; batched over layers via blockIdx.z
__global__ __launch_bounds__(256) void wprep(const float* __restrict__ W,
    __half* __restrict__ Wh, int K, int N, size_t wstride, size_t ostride) {
    __shared__ float s[32 * 128];
    const int i = blockIdx.x, j = blockIdx.y, l = blockIdx.z;
    W  += (size_t)l * wstride;
    Wh += (size_t)l * ostride;
    #pragma unroll
    for (int e = 0; e < 16; e++) {
        int idx = threadIdx.x + e * 256;
        int kk = idx >> 7, r = idx & 127;
        s[kk * 128 + r] = W[(size_t)(j * 32 + kk) * N + i * 128 + r];
    }
    __syncthreads();
    const size_t tbase = ((size_t)i * (K >> 5) + j) * 4096;
    #pragma unroll
    for (int e = 0; e < 2; e++) {
        int q = threadIdx.x * 2 + e;
        int r = q >> 2, cp = q & 3;
        int c = cp ^ ((r >> 1) & 3);
        uint32_t hw[4];
        #pragma unroll
        for (int u = 0; u < 4; u++) {
            __half2 hp = __floats2half2_rn(s[(c * 8 + 2 * u) * 128 + r],
                                           s[(c * 8 + 2 * u + 1) * 128 + r]);
            hw[u] = *(uint32_t*)&hp;
        }
        *(uint4*)(Wh + tbase + r * 32 + cp * 8) = make_uint4(hw[0], hw[1], hw[2], hw[3]);
    }
}

// fp32 [M,1024] row-major -> tile-major fp16
__global__ void split_tile(const float* __restrict__ s, __half* __restrict__ hi) {
    int idx = blockIdx.x * 256 + threadIdx.x;
    int row = idx >> 10, d = idx & 1023;
    hi[tile_off(row, d, Dc)] = __float2half(s[idx]);
}

__global__ void copy_kernel(const float* __restrict__ src, float* __restrict__ dst, int n) {
    int i = blockIdx.x * blockDim.x + threadIdx.x;
    if (i < n) dst[i] = src[i];
}
__global__ void silu_kernel(const float* __restrict__ c, float* __restrict__ out, int n) {
    int i = blockIdx.x * blockDim.x + threadIdx.x;
    if (i < n) { float x = c[i]; out[i] = x / (1.f + expf(-x)); }
}
__device__ __forceinline__ float block_reduce_sum(float v, float* red) {
    int tid = threadIdx.x;
    red[tid] = v;
    __syncthreads();
    #pragma unroll
    for (int s = 128; s > 0; s >>= 1) {
        if (tid < s) red[tid] += red[tid + s];
        __syncthreads();
    }
    float r = red[0];
    __syncthreads();
    return r;
}

__global__ void ln_mod(const float* __restrict__ x, const float* __restrict__ ada,
                       int off_shift, int off_scale, __half* __restrict__ hi) {
    __shared__ float red[256];
    int row = blockIdx.x, b = row / Tc, tid = threadIdx.x;
    const float* xr = x + (size_t)row * Dc;
    float v[4], s = 0.f;
    #pragma unroll
    for (int i = 0; i < 4; i++) { v[i] = xr[tid + i * 256]; s += v[i]; }
    float mean = block_reduce_sum(s, red) * (1.f / 1024.f);
    float sq = 0.f;
    #pragma unroll
    for (int i = 0; i < 4; i++) { float d = v[i] - mean; sq += d * d; }
    float rstd = rsqrtf(block_reduce_sum(sq, red) * (1.f / 1024.f) + 1e-5f);
    const float* ab = ada + (size_t)b * 6 * Dc;
    #pragma unroll
    for (int i = 0; i < 4; i++) {
        int d = tid + i * 256;
        float o = (v[i] - mean) * rstd * (1.f + ab[off_scale + d]) + ab[off_shift + d];
        hi[tile_off(row, d, Dc)] = __float2half(o);
    }
}

// RMSNorm + RoPE: read plain fp16 [(b*H+h)*S + s][64], write swizzled fp16 same indexing
__global__ void rmsrope_h2(const __half* __restrict__ in, const float* __restrict__ w,
                           int sLog, float cmul, const float* __restrict__ gate,
                           __half* __restrict__ outh) {
    int warp = (blockIdx.x * blockDim.x + threadIdx.x) >> 5;
    int lane = threadIdx.x & 31;
    int s = warp & ((1 << sLog) - 1);
    const __half* p = in + (size_t)warp * 64;
    float x0 = __half2float(p[lane]);
    float x1 = __half2float(p[lane + 32]);
    float ss = x0 * x0 + x1 * x1;
    #pragma unroll
    for (int o = 16; o; o >>= 1) ss += __shfl_xor_sync(0xffffffffu, ss, o);
    float inv = rsqrtf(ss * (1.f / 64.f) + 1e-6f);
    x0 = x0 * inv * w[lane];
    x1 = x1 * inv * w[lane + 32];
    float fr = (float)s * expf(-(float)lane * 0.28782313662425575f);
    float c = cosf(fr), sn = sinf(fr);
    float mult = cmul;
    if (gate) mult *= 1.f / (1.f + expf(-gate[0]));
    size_t base = ((size_t)warp - s) * 64;
    outh[base + tile_off(s, lane, 64)]      = __float2half((x0 * c - x1 * sn) * mult);
    outh[base + tile_off(s, lane + 32, 64)] = __float2half((x1 * c + x0 * sn) * mult);
}

// batched over layers via blockIdx.z
__global__ void small_gemm_kernel(const float* __restrict__ A, const float* __restrict__ W,
                                  const float* __restrict__ bias, float* __restrict__ C,
                                  int Nn, int Kk, size_t wstride, size_t bstride, size_t cstride) {
    int l = blockIdx.z;
    W    += (size_t)l * wstride;
    bias += (size_t)l * bstride;
    C    += (size_t)l * cstride;
    int n = blockIdx.x * blockDim.x + threadIdx.x;
    int b = blockIdx.y;
    if (n >= Nn) return;
    const float* a = A + (size_t)b * Kk;
    float acc = 0.f;
    #pragma unroll 4
    for (int k = 0; k < Kk; k++) acc += a[k] * W[(size_t)k * Nn + n];
    C[(size_t)b * Nn + n] = acc + bias[n];
}

// ---- fp16 tensor-core flash attention ----
#define FSMEM (16384 + 2*32768 + 64)
__global__ __launch_bounds__(256) void flash_mma(
    const __half* __restrict__ qh,
    const __half* __restrict__ ksh, const __half* __restrict__ vsh,
    const __half* __restrict__ kah, const __half* __restrict__ vah,
    const __half* __restrict__ kth, const __half* __restrict__ vth,
    __half* __restrict__ oh)
{
    extern __shared__ __align__(128) char smem[];
    const int tid = threadIdx.x, w = tid >> 5, lane = tid & 31;
    const int g = lane >> 2, t = lane & 3;
    const int bh = blockIdx.y, b = bh >> 4, h = bh & 15;
    const int qt = blockIdx.x;
    const uint32_t sb = smem_u32(smem);
    const uint32_t mbQ = sb + 81920, mbF = mbQ + 8;

    const __half* Ksrc[7];
    const __half* Vsrc[7];
    {
        const __half* kb = ksh + (size_t)bh * (Tc * 64);
        const __half* vb = vsh + (size_t)bh * (Tc * 64);
        Ksrc[0] = kb;         Vsrc[0] = vb;
        Ksrc[1] = kb + 8192;  Vsrc[1] = vb + 8192;
        const __half* ka = kah + (size_t)bh * (SAc * 64);
        const __half* va = vah + (size_t)bh * (SAc * 64);
        #pragma unroll
        for (int j = 0; j < 4; j++) { Ksrc[2 + j] = ka + j * 8192; Vsrc[2 + j] = va + j * 8192; }
        Ksrc[6] = kth + (size_t)bh * (STc * 64);
        Vsrc[6] = vth + (size_t)bh * (STc * 64);
    }

    auto issue = [&](int slot, int blk) {
        uint32_t kd = sb + 16384 + slot * 32768;
        uint32_t bar = mbF + 8 * slot;
        MBAR_EXPECT(bar, 32768u);
        BULK8K(kd,          Ksrc[blk],        bar);
        BULK8K(kd + 8192,   Ksrc[blk] + 4096, bar);
        BULK8K(kd + 16384,  Vsrc[blk],        bar);
        BULK8K(kd + 24576,  Vsrc[blk] + 4096, bar);
    };

    if (tid == 0) {
        MBAR_INIT(mbQ, 1);
        MBAR_INIT(mbF, 1);
        MBAR_INIT(mbF + 8, 1);
        FENCE_ASYNC();
        MBAR_EXPECT(mbQ, 16384u);
        const __half* qsrc = qh + (size_t)bh * (Tc * 64) + qt * 8192;
        BULK8K(sb,        qsrc,        mbQ);
        BULK8K(sb + 8192, qsrc + 4096, mbQ);
        issue(0, 0);
        issue(1, 1);
    }
    __syncthreads();

    const int ra  = (lane & 7) + ((lane >> 3) & 1) * 8;
    const int sa  = lane >> 4;
    const int rbn = (lane & 7) + (lane >> 4) * 8;
    const int sbk = (lane >> 3) & 1;
    const int rvk = (lane & 7) + ((lane >> 3) & 1) * 8;
    const int svd = (lane >> 4) & 1;

    MBAR_WAIT(mbQ, 0);
    uint32_t qa[4][4];
    #pragma unroll
    for (int ks = 0; ks < 4; ks++)
        LDSM4(qa[ks], sb + 2 * (uint32_t)tile_off(16 * w + ra, ks * 16 + sa * 8, 64));

    float sO[8][4];
    #pragma unroll
    for (int i = 0; i < 8; i++)
        #pragma unroll
        for (int e = 0; e < 4; e++) sO[i][e] = 0.f;
    float m0 = -1e30f, m1 = -1e30f, l0 = 0.f, l1 = 0.f;

    for (int blk = 0; blk < 7; blk++) {
        const int slot = blk & 1;
        MBAR_WAIT(mbF + 8 * slot, (blk >> 1) & 1);
        const uint32_t kbase = sb + 16384 + slot * 32768;
        const uint32_t vbase = kbase + 16384;

        float sc[16][4];
        #pragma unroll
        for (int i = 0; i < 16; i++)
            #pragma unroll
            for (int e = 0; e < 4; e++) sc[i][e] = 0.f;

        #pragma unroll
        for (int ks = 0; ks < 4; ks++) {
            #pragma unroll
            for (int np = 0; np < 8; np++) {
                uint32_t b4[4];
                LDSM4(b4, kbase + 2 * (uint32_t)tile_off(16 * np + rbn, ks * 16 + sbk * 8, 64));
                mma_f16(sc[2 * np],     qa[ks], &b4[0]);
                mma_f16(sc[2 * np + 1], qa[ks], &b4[2]);
            }
        }

        float tm0 = -1e30f, tm1 = -1e30f;
        #pragma unroll
        for (int i = 0; i < 16; i++) {
            tm0 = fmaxf(tm0, fmaxf(sc[i][0], sc[i][1]));
            tm1 = fmaxf(tm1, fmaxf(sc[i][2], sc[i][3]));
        }
        tm0 = fmaxf(tm0, __shfl_xor_sync(0xffffffffu, tm0, 1));
        tm0 = fmaxf(tm0, __shfl_xor_sync(0xffffffffu, tm0, 2));
        tm1 = fmaxf(tm1, __shfl_xor_sync(0xffffffffu, tm1, 1));
        tm1 = fmaxf(tm1, __shfl_xor_sync(0xffffffffu, tm1, 2));
        float nm0 = fmaxf(m0, tm0), nm1 = fmaxf(m1, tm1);
        float cr0 = __expf(m0 - nm0), cr1 = __expf(m1 - nm1);
        l0 *= cr0; l1 *= cr1;
        #pragma unroll
        for (int i = 0; i < 8; i++) {
            sO[i][0] *= cr0; sO[i][1] *= cr0;
            sO[i][2] *= cr1; sO[i][3] *= cr1;
        }
        m0 = nm0; m1 = nm1;

        uint32_t pf[16][2];
        #pragma unroll
        for (int i = 0; i < 16; i++) {
            float p0 = __expf(sc[i][0] - nm0), p1 = __expf(sc[i][1] - nm0);
            float p2 = __expf(sc[i][2] - nm1), p3 = __expf(sc[i][3] - nm1);
            l0 += p0 + p1;
            l1 += p2 + p3;
            __half2 h0 = __floats2half2_rn(p0, p1), h1 = __floats2half2_rn(p2, p3);
            pf[i][0] = *(uint32_t*)&h0;
            pf[i][1] = *(uint32_t*)&h1;
        }

        #pragma unroll
        for (int u = 0; u < 8; u++) {
            uint32_t pa[4] = {pf[2*u][0], pf[2*u][1], pf[2*u+1][0], pf[2*u+1][1]};
            #pragma unroll
            for (int nd = 0; nd < 4; nd++) {
                uint32_t vb4[4];
                LDSM4T(vb4, vbase + 2 * (uint32_t)tile_off(16 * u + rvk, 16 * nd + svd * 8, 64));
                mma_f16(sO[2 * nd],     pa, &vb4[0]);
                mma_f16(sO[2 * nd + 1], pa, &vb4[2]);
            }
        }
        __syncthreads();
        if (tid == 0 && blk + 2 < 7) { FENCE_ASYNC(); issue(slot, blk + 2); }
    }

    l0 += __shfl_xor_sync(0xffffffffu, l0, 1);
    l0 += __shfl_xor_sync(0xffffffffu, l0, 2);
    l1 += __shfl_xor_sync(0xffffffffu, l1, 1);
    l1 += __shfl_xor_sync(0xffffffffu, l1, 2);
    float i0 = 1.f / l0, i1 = 1.f / l1;

    int orow = b * Tc + qt * 128 + 16 * w + g;
    #pragma unroll
    for (int nt = 0; nt < 8; nt++) {
        int col = h * 64 + nt * 8 + 2 * t;
        __half2 v0 = __floats2half2_rn(sO[nt][0] * i0, sO[nt][1] * i0);
        __half2 v1 = __floats2half2_rn(sO[nt][2] * i1, sO[nt][3] * i1);
        *(__half2*)(oh + tile_off(orow, col, Dc))     = v0;
        *(__half2*)(oh + tile_off(orow + 8, col, Dc)) = v1;
    }
}

__global__ void final_kernel(const float* __restrict__ x, const float* __restrict__ lw,
                             const float* __restrict__ lb, const float* __restrict__ Wout,
                             const float* __restrict__ bout, float* __restrict__ out) {
    __shared__ float red[256];
    int row = blockIdx.x, tid = threadIdx.x;
    const float* xr = x + (size_t)row * Dc;
    float v[4], s = 0.f;
    #pragma unroll
    for (int i = 0; i < 4; i++) { v[i] = xr[tid + i * 256]; s += v[i]; }
    float mean = block_reduce_sum(s, red) * (1.f / 1024.f);
    float sq = 0.f;
    #pragma unroll
    for (int i = 0; i < 4; i++) { float d = v[i] - mean; sq += d * d; }
    float rstd = rsqrtf(block_reduce_sum(sq, red) * (1.f / 1024.f) + 1e-5f);
    float p0 = 0.f, p1 = 0.f, p2 = 0.f;
    #pragma unroll
    for (int i = 0; i < 4; i++) {
        int d = tid + i * 256;
        float y = (v[i] - mean) * rstd * lw[d] + lb[d];
        p0 = fmaf(y, Wout[d * OUTc + 0], p0);
        p1 = fmaf(y, Wout[d * OUTc + 1], p1);
        p2 = fmaf(y, Wout[d * OUTc + 2], p2);
    }
    p0 = block_reduce_sum(p0, red);
    p1 = block_reduce_sum(p1, red);
    p2 = block_reduce_sum(p2, red);
    if (tid == 0) {
        out[row * OUTc + 0] = p0 + bout[0];
        out[row * OUTc + 1] = p1 + bout[1];
        out[row * OUTc + 2] = p2 + bout[2];
    }
}

extern "C" void kernel_launch(void* const* d_in, const int* in_sizes, int n_in,
                              void* d_out, int out_size)
{
    (void)in_sizes; (void)n_in; (void)out_size;
    const float* x    = (const float*)d_in[0];
    const float* cond = (const float*)d_in[1];
    const float* adp  = (const float*)d_in[2];
    const float* task = (const float*)d_in[3];
    const float* Wq   = (const float*)d_in[4];
    const float* bq   = (const float*)d_in[5];
    const float* Wks  = (const float*)d_in[6];
    const float* Wvs  = (const float*)d_in[7];
    const float* Wka  = (const float*)d_in[8];
    const float* Wva  = (const float*)d_in[9];
    const float* Wkt  = (const float*)d_in[10];
    const float* Wvt  = (const float*)d_in[11];
    const float* Wo   = (const float*)d_in[12];
    const float* bo   = (const float*)d_in[13];
    const float* qnw  = (const float*)d_in[14];
    const float* knw  = (const float*)d_in[15];
    const float* gate = (const float*)d_in[16];
    const float* Wada = (const float*)d_in[17];
    const float* bada = (const float*)d_in[18];
    const float* W1   = (const float*)d_in[19];
    const float* b1   = (const float*)d_in[20];
    const float* W2   = (const float*)d_in[21];
    const float* b2   = (const float*)d_in[22];
    const float* lnfw = (const float*)d_in[23];
    const float* lnfb = (const float*)d_in[24];
    const float* Wout = (const float*)d_in[25];
    const float* bout = (const float*)d_in[26];
    float* out = (float*)d_out;

    cudaFuncSetAttribute(mma_gemm<0>, cudaFuncAttributeMaxDynamicSharedMemorySize, GSMEM);
    cudaFuncSetAttribute(mma_gemm<1>, cudaFuncAttributeMaxDynamicSharedMemorySize, GSMEM);
    cudaFuncSetAttribute(mma_gemm<2>, cudaFuncAttributeMaxDynamicSharedMemorySize, GSMEM);
    cudaFuncSetAttribute(mma_gemm<4>, cudaFuncAttributeMaxDynamicSharedMemorySize, GSMEM);
    cudaFuncSetAttribute(flash_mma,   cudaFuncAttributeMaxDynamicSharedMemorySize, FSMEM);

    float *px, *pada, *psc;
    __half *ph, *po, *pf, *pa, *pt, *pw;
    __half *pqp, *pksp, *pkap, *pktp;
    __half *pqh, *pksh, *pvsh, *pkah, *pvah, *pkth, *pvth;
    cudaGetSymbolAddress((void**)&px,  g_x);
    cudaGetSymbolAddress((void**)&pada, g_ada);
    cudaGetSymbolAddress((void**)&psc,  g_sc);
    cudaGetSymbolAddress((void**)&ph, g_h);
    cudaGetSymbolAddress((void**)&po, g_o);
    cudaGetSymbolAddress((void**)&pf, g_ff);
    cudaGetSymbolAddress((void**)&pa, g_adp);
    cudaGetSymbolAddress((void**)&pt, g_tsk);
    cudaGetSymbolAddress((void**)&pw, g_w);
    cudaGetSymbolAddress((void**)&pqp,  g_qp);
    cudaGetSymbolAddress((void**)&pksp, g_ksp);
    cudaGetSymbolAddress((void**)&pkap, g_kap);
    cudaGetSymbolAddress((void**)&pktp, g_ktp);
    cudaGetSymbolAddress((void**)&pqh,  g_qh);
    cudaGetSymbolAddress((void**)&pksh, g_ksh);
    cudaGetSymbolAddress((void**)&pvsh, g_vsh);
    cudaGetSymbolAddress((void**)&pkah, g_kah);
    cudaGetSymbolAddress((void**)&pvah, g_vah);
    cudaGetSymbolAddress((void**)&pkth, g_kth);
    cudaGetSymbolAddress((void**)&pvth, g_vth);

    copy_kernel<<<(MTc*Dc)/256, 256>>>(x, px, MTc*Dc);
    silu_kernel<<<(Bc*Dc)/256, 256>>>(cond, psc, Bc*Dc);
    split_tile<<<(MAc*Dc)/256, 256>>>(adp,  pa);
    split_tile<<<(MSc*Dc)/256, 256>>>(task, pt);

    // batched weight prep: one launch per matrix type, all 6 layers in grid.z
    const float* wsrc[8] = {Wq, Wks, Wvs, Wka, Wva, Wkt, Wvt, Wo};
    for (int mtx = 0; mtx < 8; mtx++)
        wprep<<<dim3(Dc/128, Dc/32, Lc), 256>>>(
            wsrc[mtx], pw + (size_t)mtx * DDc, Dc, Dc, (size_t)DDc, (size_t)WPLc);
    wprep<<<dim3(DFFc/128, Dc/32, Lc), 256>>>(
        W1, pw + 8*(size_t)DDc, Dc, DFFc, (size_t)Dc*DFFc, (size_t)WPLc);
    wprep<<<dim3(Dc/128, DFFc/32, Lc), 256>>>(
        W2, pw + 8*(size_t)DDc + (size_t)Dc*DFFc, DFFc, Dc, (size_t)DFFc*Dc, (size_t)WPLc);

    // batched ada for all layers
    small_gemm_kernel<<<dim3((6*Dc)/256, Bc, Lc), 256>>>(
        psc, Wada, bada, pada, 6*Dc, Dc,
        (size_t)Dc*6*Dc, (size_t)6*Dc, (size_t)ADAL);

    for (int i = 0; i < Lc; i++) {
        size_t wb = (size_t)i * WPLc;
        __half* wqkv = pw + wb;                       // q,k,v weights contiguous
        __half* wka2 = pw + wb + 3*(size_t)DDc;       // ka,va contiguous
        __half* wkt2 = pw + wb + 5*(size_t)DDc;       // kt,vt contiguous
        __half* wo2  = pw + wb + 7*(size_t)DDc;
        __half* w1   = pw + wb + 8*(size_t)DDc;
        __half* w2   = pw + wb + 8*(size_t)DDc + (size_t)Dc*DFFc;
        float* padaL = pada + (size_t)i * ADAL;

        ln_mod<<<MTc, 256>>>(px, padaL, 0, Dc, ph);

        // fused Q|K|V (bias on Q only), fused adp K|V, fused task K|V
        mma_gemm<4><<<dim3(3*Dc/128, MTc/128), 256, GSMEM>>>(ph, wqkv, bq + (size_t)i*Dc, nullptr,
            MTc, 3*Dc, Dc, nullptr, 0, nullptr, pqp, pksp, pvsh, 8);
        mma_gemm<4><<<dim3(2*Dc/128, MAc/128), 256, GSMEM>>>(pa, wka2, nullptr, nullptr,
            MAc, 2*Dc, Dc, nullptr, 0, nullptr, pkap, nullptr, pvah, 9);
        mma_gemm<4><<<dim3(2*Dc/128, MSc/128), 256, GSMEM>>>(pt, wkt2, nullptr, nullptr,
            MSc, 2*Dc, Dc, nullptr, 0, nullptr, pktp, nullptr, pvth, 7);

        rmsrope_h2<<<(MTc*Hc*32)/256, 256>>>(pqp,  qnw + (size_t)i*HDc, 8, 0.125f, nullptr, pqh);
        rmsrope_h2<<<(MTc*Hc*32)/256, 256>>>(pksp, knw + (size_t)i*HDc, 8, 1.f,    nullptr, pksh);
        rmsrope_h2<<<(MAc*Hc*32)/256, 256>>>(pkap, knw + (size_t)i*HDc, 9, 1.f,    nullptr, pkah);
        rmsrope_h2<<<(MSc*Hc*32)/256, 256>>>(pktp, knw + (size_t)i*HDc, 7, 1.f,    gate + i, pkth);

        flash_mma<<<dim3(Tc/128, Bc*Hc), 256, FSMEM>>>(pqh, pksh, pvsh, pkah, pvah, pkth, pvth, po);

        mma_gemm<2><<<dim3(Dc/128, MTc/128), 256, GSMEM>>>(po, wo2, bo + (size_t)i*Dc, nullptr,
            MTc, Dc, Dc, padaL + 2*Dc, 6*Dc, px, nullptr, nullptr, nullptr, 0);

        ln_mod<<<MTc, 256>>>(px, padaL, 3*Dc, 4*Dc, ph);

        mma_gemm<1><<<dim3(DFFc/128, MTc/128), 256, GSMEM>>>(ph, w1, b1 + (size_t)i*DFFc, nullptr,
            MTc, DFFc, Dc, nullptr, 0, nullptr, pf, nullptr, nullptr, 0);

        mma_gemm<2><<<dim3(Dc/128, MTc/128), 256, GSMEM>>>(pf, w2, b2 + (size_t)i*Dc, nullptr,
            MTc, Dc, DFFc, padaL + 5*Dc, 6*Dc, px, nullptr, nullptr, nullptr, 0);
    }

    final_kernel<<<MTc, 256>>>(px, lnfw, lnfb, Wout, bout, out);
}